// round 1
// baseline (speedup 1.0000x reference)
#include <cuda_runtime.h>
#include <math.h>

#define NPTS 131072
#define MSEG 4096
#define CCH  32
#define MIDD 16
#define KNB  6
#define ACCW 36   // 32 fea + 3 xyz + 1 wsum, stride 144B (16B aligned)

// ---------------- scratch (static device globals; no allocation) ----------------
__device__ __align__(256) float g_sphf[MSEG * MIDD];   // sp_fea @ wf1_w^T (no bias)
__device__ __align__(256) float g_sphx[MSEG * MIDD];   // sp_xyz @ wx1_w^T (no bias)
__device__ __align__(256) float g_acc [MSEG * ACCW];   // segment accumulators

// ---------------- kernel 0: zero accumulators ----------------
__global__ void zero_acc_kernel() {
    int i = blockIdx.x * blockDim.x + threadIdx.x;
    if (i < MSEG * ACCW) g_acc[i] = 0.0f;
}

// ---------------- kernel 1: per-superpoint first-layer precompute ----------------
__global__ void sp_pre_kernel(const float* __restrict__ sp_fea,
                              const float* __restrict__ sp_xyz,
                              const float* __restrict__ wf1w,   // (MID, C)
                              const float* __restrict__ wx1w) { // (MID, 3)
    int m = blockIdx.x * blockDim.x + threadIdx.x;
    if (m >= MSEG) return;
    float fea[CCH];
#pragma unroll
    for (int c = 0; c < CCH; c += 4) {
        float4 v = *reinterpret_cast<const float4*>(sp_fea + m * CCH + c);
        fea[c] = v.x; fea[c + 1] = v.y; fea[c + 2] = v.z; fea[c + 3] = v.w;
    }
    float x0 = sp_xyz[m * 3 + 0], x1 = sp_xyz[m * 3 + 1], x2 = sp_xyz[m * 3 + 2];
#pragma unroll
    for (int i = 0; i < MIDD; i++) {
        float s = 0.f;
#pragma unroll
        for (int c = 0; c < CCH; c++) s += fea[c] * __ldg(wf1w + i * CCH + c);
        g_sphf[m * MIDD + i] = s;
        g_sphx[m * MIDD + i] = x0 * __ldg(wx1w + i * 3 + 0)
                             + x1 * __ldg(wx1w + i * 3 + 1)
                             + x2 * __ldg(wx1w + i * 3 + 2);
    }
}

// ---------------- kernel 2: main per-point kernel ----------------
struct SmemB {
    float m1w [CCH * CCH];    // mlp1_w (C,C) row-major [c_out*32+c_in]
    float m2w [CCH * CCH];    // mlp2_w
    float wf1w[MIDD * CCH];   // (MID, C)
    float wf2w[CCH * MIDD];   // (C, MID) row-major [c*16+i]
    float wx2w[CCH * MIDD];
    float wx1w[MIDD * 3];
    float Gf[MIDD * MIDD];    // wf2_w^T wf2_w
    float Gx[MIDD * MIDD];
    float gf[MIDD], gx[MIDD]; // wf2_w^T b2
    float af[MIDD], betf[MIDD];   // folded BN for wf path (bias folded in)
    float ax[MIDD], betx[MIDD];
    float am[CCH], bm[CCH];       // folded BN for mlp path
    float m2b[CCH], wf2b[CCH], wx2b[CCH];
    float cf, cx;                 // ||b2||^2
};

__global__ void __launch_bounds__(256) main_kernel(
    const float* __restrict__ o_p_fea, const float* __restrict__ p_xyz,
    const int*   __restrict__ idx_abs, const int*  __restrict__ idx_rel,
    const float* __restrict__ wf1w, const float* __restrict__ wf1b,
    const float* __restrict__ wfg,  const float* __restrict__ wfb,
    const float* __restrict__ wfm,  const float* __restrict__ wfv,
    const float* __restrict__ wf2w, const float* __restrict__ wf2b,
    const float* __restrict__ wx1w, const float* __restrict__ wx1b,
    const float* __restrict__ wxg,  const float* __restrict__ wxb,
    const float* __restrict__ wxm,  const float* __restrict__ wxv,
    const float* __restrict__ wx2w, const float* __restrict__ wx2b,
    const float* __restrict__ m1w,  const float* __restrict__ m1b,
    const float* __restrict__ mg,   const float* __restrict__ mbb,
    const float* __restrict__ mm,   const float* __restrict__ mv,
    const float* __restrict__ m2w,  const float* __restrict__ m2b)
{
    __shared__ SmemB sm;
    const int tid = threadIdx.x;

    // -------- phase 1: load weights, fold BN --------
    for (int i = tid; i < CCH * CCH; i += 256) { sm.m1w[i] = m1w[i]; sm.m2w[i] = m2w[i]; }
    for (int i = tid; i < MIDD * CCH; i += 256) {
        sm.wf1w[i] = wf1w[i]; sm.wf2w[i] = wf2w[i]; sm.wx2w[i] = wx2w[i];
    }
    if (tid < MIDD * 3) sm.wx1w[tid] = wx1w[tid];
    if (tid < MIDD) {
        float a  = wfg[tid] * rsqrtf(wfv[tid] + 1e-5f);
        sm.af[tid]   = a;
        sm.betf[tid] = a * (wf1b[tid] - wfm[tid]) + wfb[tid];
        float a2 = wxg[tid] * rsqrtf(wxv[tid] + 1e-5f);
        sm.ax[tid]   = a2;
        sm.betx[tid] = a2 * (wx1b[tid] - wxm[tid]) + wxb[tid];
    }
    if (tid < CCH) {
        float a = mg[tid] * rsqrtf(mv[tid] + 1e-5f);
        sm.am[tid] = a;
        sm.bm[tid] = a * (m1b[tid] - mm[tid]) + mbb[tid];
        sm.m2b[tid]  = m2b[tid];
        sm.wf2b[tid] = wf2b[tid];
        sm.wx2b[tid] = wx2b[tid];
    }
    __syncthreads();

    // -------- phase 2: Gram matrices for the norm trick --------
    {
        int i = tid >> 4, j = tid & 15;
        float sf = 0.f, sx = 0.f;
#pragma unroll
        for (int c = 0; c < CCH; c++) {
            sf += sm.wf2w[c * MIDD + i] * sm.wf2w[c * MIDD + j];
            sx += sm.wx2w[c * MIDD + i] * sm.wx2w[c * MIDD + j];
        }
        sm.Gf[tid] = sf; sm.Gx[tid] = sx;
        if (tid < MIDD) {
            float s = 0.f;
            for (int c = 0; c < CCH; c++) s += sm.wf2w[c * MIDD + tid] * sm.wf2b[c];
            sm.gf[tid] = s;
        } else if (tid < 2 * MIDD) {
            int t = tid - MIDD; float s = 0.f;
            for (int c = 0; c < CCH; c++) s += sm.wx2w[c * MIDD + t] * sm.wx2b[c];
            sm.gx[t] = s;
        } else if (tid == 32) {
            float s = 0.f;
            for (int c = 0; c < CCH; c++) s += sm.wf2b[c] * sm.wf2b[c];
            sm.cf = s;
        } else if (tid == 33) {
            float s = 0.f;
            for (int c = 0; c < CCH; c++) s += sm.wx2b[c] * sm.wx2b[c];
            sm.cx = s;
        }
    }
    __syncthreads();

    const int n = blockIdx.x * blockDim.x + tid;   // N = 512*256 exactly

    // -------- per-point MLP: p_fea = l2norm(mlp(o_p_fea)) --------
    float p0[CCH];
#pragma unroll
    for (int c = 0; c < CCH; c += 4) {
        float4 v = *reinterpret_cast<const float4*>(o_p_fea + (size_t)n * CCH + c);
        p0[c] = v.x; p0[c + 1] = v.y; p0[c + 2] = v.z; p0[c + 3] = v.w;
    }
    float h1[CCH];
#pragma unroll
    for (int c = 0; c < CCH; c++) {
        float s = 0.f;
#pragma unroll
        for (int c2 = 0; c2 < CCH; c2++) s += p0[c2] * sm.m1w[c * CCH + c2];
        h1[c] = fmaxf(sm.am[c] * s + sm.bm[c], 0.f);
    }
    float pf[CCH]; float ss = 0.f;
#pragma unroll
    for (int c = 0; c < CCH; c++) {
        float s = sm.m2b[c];
#pragma unroll
        for (int c2 = 0; c2 < CCH; c2++) s += h1[c2] * sm.m2w[c * CCH + c2];
        pf[c] = s; ss += s * s;
    }
    float inv = 1.f / fmaxf(sqrtf(ss), 1e-12f);

    // V = p_norm @ W2 (per point), pb = p_norm . b2
    float Vf[MIDD], Vx[MIDD];
#pragma unroll
    for (int i = 0; i < MIDD; i++) {
        float sf = 0.f, sx = 0.f;
#pragma unroll
        for (int c = 0; c < CCH; c++) {
            sf += pf[c] * sm.wf2w[c * MIDD + i];
            sx += pf[c] * sm.wx2w[c * MIDD + i];
        }
        Vf[i] = sf * inv; Vx[i] = sx * inv;
    }
    float pbf = 0.f, pbx = 0.f;
#pragma unroll
    for (int c = 0; c < CCH; c++) { pbf += pf[c] * sm.wf2b[c]; pbx += pf[c] * sm.wx2b[c]; }
    pbf *= inv; pbx *= inv;

    // first-layer projections of the point itself
    float PHf[MIDD];
#pragma unroll
    for (int i = 0; i < MIDD; i++) {
        float s = 0.f;
#pragma unroll
        for (int c = 0; c < CCH; c++) s += p0[c] * sm.wf1w[i * CCH + c];
        PHf[i] = s;
    }
    const float x0 = p_xyz[(size_t)n * 3 + 0];
    const float x1 = p_xyz[(size_t)n * 3 + 1];
    const float x2 = p_xyz[(size_t)n * 3 + 2];
    float PHx[MIDD];
#pragma unroll
    for (int i = 0; i < MIDD; i++)
        PHx[i] = x0 * sm.wx1w[i * 3 + 0] + x1 * sm.wx1w[i * 3 + 1] + x2 * sm.wx1w[i * 3 + 2];

    // -------- K candidates: scores --------
    float sc[KNB];
#pragma unroll
    for (int k = 0; k < KNB; k++) {
        int idx = idx_abs[(size_t)n * KNB + k];
        float hf[MIDD], hx[MIDD];
#pragma unroll
        for (int i = 0; i < MIDD; i += 4) {
            float4 v = *reinterpret_cast<const float4*>(g_sphf + (size_t)idx * MIDD + i);
            hf[i] = v.x; hf[i + 1] = v.y; hf[i + 2] = v.z; hf[i + 3] = v.w;
            float4 u = *reinterpret_cast<const float4*>(g_sphx + (size_t)idx * MIDD + i);
            hx[i] = u.x; hx[i + 1] = u.y; hx[i + 2] = u.z; hx[i + 3] = u.w;
        }
#pragma unroll
        for (int i = 0; i < MIDD; i++) {
            hf[i] = fmaxf(sm.af[i] * (hf[i] - PHf[i]) + sm.betf[i], 0.f);
            hx[i] = fmaxf(sm.ax[i] * (hx[i] - PHx[i]) + sm.betx[i], 0.f);
        }
        float df = pbf, dx = pbx, qf = sm.cf, qx = sm.cx;
#pragma unroll
        for (int i = 0; i < MIDD; i++) { df += hf[i] * Vf[i]; dx += hx[i] * Vx[i]; }
#pragma unroll
        for (int i = 0; i < MIDD; i++) {
            float tf = 2.f * sm.gf[i], tx = 2.f * sm.gx[i];
#pragma unroll
            for (int j = 0; j < MIDD; j++) {
                tf += sm.Gf[i * MIDD + j] * hf[j];
                tx += sm.Gx[i * MIDD + j] * hx[j];
            }
            qf += hf[i] * tf; qx += hx[i] * tx;
        }
        float nf = fmaxf(sqrtf(fmaxf(qf, 0.f)), 1e-12f);
        float nx = fmaxf(sqrtf(fmaxf(qx, 0.f)), 1e-12f);
        sc[k] = (df / nf) * (dx / nx);
    }

    // -------- softmax over K --------
    float mx = sc[0];
#pragma unroll
    for (int k = 1; k < KNB; k++) mx = fmaxf(mx, sc[k]);
    float esum = 0.f;
#pragma unroll
    for (int k = 0; k < KNB; k++) { sc[k] = __expf(sc[k] - mx); esum += sc[k]; }
    float isum = 1.f / esum;

    // -------- scatter into segment accumulators (vector reds) --------
#pragma unroll
    for (int k = 0; k < KNB; k++) {
        int seg = idx_rel[(size_t)n * KNB + k];
        float wk = sc[k] * isum;
        float* base = g_acc + (size_t)seg * ACCW;
#pragma unroll
        for (int c = 0; c < CCH; c += 4) {
            asm volatile("red.global.add.v4.f32 [%0], {%1,%2,%3,%4};"
                         :: "l"(base + c),
                            "f"(p0[c] * wk), "f"(p0[c + 1] * wk),
                            "f"(p0[c + 2] * wk), "f"(p0[c + 3] * wk)
                         : "memory");
        }
        asm volatile("red.global.add.v4.f32 [%0], {%1,%2,%3,%4};"
                     :: "l"(base + CCH),
                        "f"(x0 * wk), "f"(x1 * wk), "f"(x2 * wk), "f"(wk)
                     : "memory");
    }
}

// ---------------- kernel 3: finalize ----------------
__global__ void finalize_kernel(float* __restrict__ out) {
    int m = blockIdx.x * blockDim.x + threadIdx.x;
    if (m >= MSEG) return;
    float d = 1.f / (g_acc[m * ACCW + 35] + 1e-8f);
#pragma unroll
    for (int c = 0; c < CCH; c++) out[m * CCH + c] = g_acc[m * ACCW + c] * d;
#pragma unroll
    for (int j = 0; j < 3; j++) out[MSEG * CCH + m * 3 + j] = g_acc[m * ACCW + CCH + j] * d;
}

// ---------------- launch ----------------
extern "C" void kernel_launch(void* const* d_in, const int* in_sizes, int n_in,
                              void* d_out, int out_size) {
    (void)in_sizes; (void)n_in; (void)out_size;
    const float* sp_fea  = (const float*)d_in[0];
    const float* sp_xyz  = (const float*)d_in[1];
    const float* o_p_fea = (const float*)d_in[2];
    const float* p_xyz   = (const float*)d_in[3];
    const int*   idx_abs = (const int*)d_in[4];
    const int*   idx_rel = (const int*)d_in[5];
    // d_in[6] cluster_idx, d_in[7] offset: unused by the forward output
    const float* wf1w = (const float*)d_in[8];
    const float* wf1b = (const float*)d_in[9];
    const float* wfg  = (const float*)d_in[10];
    const float* wfb  = (const float*)d_in[11];
    const float* wfm  = (const float*)d_in[12];
    const float* wfv  = (const float*)d_in[13];
    const float* wf2w = (const float*)d_in[14];
    const float* wf2b = (const float*)d_in[15];
    const float* wx1w = (const float*)d_in[16];
    const float* wx1b = (const float*)d_in[17];
    const float* wxg  = (const float*)d_in[18];
    const float* wxb  = (const float*)d_in[19];
    const float* wxm  = (const float*)d_in[20];
    const float* wxv  = (const float*)d_in[21];
    const float* wx2w = (const float*)d_in[22];
    const float* wx2b = (const float*)d_in[23];
    const float* m1w  = (const float*)d_in[24];
    const float* m1b  = (const float*)d_in[25];
    const float* mg   = (const float*)d_in[26];
    const float* mbb  = (const float*)d_in[27];
    const float* mm   = (const float*)d_in[28];
    const float* mv   = (const float*)d_in[29];
    const float* m2w  = (const float*)d_in[30];
    const float* m2b  = (const float*)d_in[31];

    zero_acc_kernel<<<(MSEG * ACCW + 255) / 256, 256>>>();
    sp_pre_kernel<<<(MSEG + 127) / 128, 128>>>(sp_fea, sp_xyz, wf1w, wx1w);
    main_kernel<<<NPTS / 256, 256>>>(
        o_p_fea, p_xyz, idx_abs, idx_rel,
        wf1w, wf1b, wfg, wfb, wfm, wfv, wf2w, wf2b,
        wx1w, wx1b, wxg, wxb, wxm, wxv, wx2w, wx2b,
        m1w, m1b, mg, mbb, mm, mv, m2w, m2b);
    finalize_kernel<<<(MSEG + 127) / 128, 128>>>((float*)d_out);
}

// round 2
// speedup vs baseline: 1.3051x; 1.3051x over previous
#include <cuda_runtime.h>
#include <math.h>

#define NPTS 131072
#define MSEG 4096
#define CCH  32
#define MIDD 16
#define KNB  6
#define ACCW 36      // 32 fea + 3 xyz + 1 wsum per segment (144B, 16B aligned)
#define RREP 4       // accumulator replicas to cut L2-atomic contention
#define BLK  128

// ---------------- static device scratch ----------------
__device__ __align__(256) float g_sphf[MSEG * MIDD];        // sp_fea @ wf1^T
__device__ __align__(256) float g_sphx[MSEG * MIDD];        // sp_xyz @ wx1^T
__device__ __align__(256) float g_acc [RREP][MSEG * ACCW];  // replicated accumulators

// ---------------- kernel 1: zero + per-superpoint first-layer precompute ----------------
__global__ void pre_kernel(const float* __restrict__ sp_fea,
                           const float* __restrict__ sp_xyz,
                           const float* __restrict__ wf1w,   // (MID, C)
                           const float* __restrict__ wx1w) { // (MID, 3)
    int m = blockIdx.x * blockDim.x + threadIdx.x;
    if (m >= MSEG) return;

    // zero this segment's accumulator rows in all replicas (vectorized)
    float4 z = make_float4(0.f, 0.f, 0.f, 0.f);
#pragma unroll
    for (int r = 0; r < RREP; r++) {
        float4* p = reinterpret_cast<float4*>(&g_acc[r][m * ACCW]);
#pragma unroll
        for (int j = 0; j < ACCW / 4; j++) p[j] = z;
    }

    float fea[CCH];
#pragma unroll
    for (int c = 0; c < CCH; c += 4) {
        float4 v = *reinterpret_cast<const float4*>(sp_fea + m * CCH + c);
        fea[c] = v.x; fea[c + 1] = v.y; fea[c + 2] = v.z; fea[c + 3] = v.w;
    }
    float x0 = sp_xyz[m * 3 + 0], x1 = sp_xyz[m * 3 + 1], x2 = sp_xyz[m * 3 + 2];
#pragma unroll
    for (int i = 0; i < MIDD; i++) {
        float s = 0.f;
#pragma unroll
        for (int c = 0; c < CCH; c++) s += fea[c] * __ldg(wf1w + i * CCH + c);
        g_sphf[m * MIDD + i] = s;
        g_sphx[m * MIDD + i] = x0 * __ldg(wx1w + i * 3 + 0)
                             + x1 * __ldg(wx1w + i * 3 + 1)
                             + x2 * __ldg(wx1w + i * 3 + 2);
    }
}

// ---------------- kernel 2: main per-point kernel ----------------
struct __align__(16) SmemB {
    float m1w [CCH * CCH];     // (C,C) row-major
    float m2w [CCH * CCH];
    float wf1w[MIDD * CCH];    // (MID, C)
    float wf2t[MIDD * CCH];    // TRANSPOSED: [i*32+c] = wf2_w[c][i]
    float wx2t[MIDD * CCH];
    float Gf[MIDD * MIDD];     // wf2^T wf2
    float Gx[MIDD * MIDD];
    float wx1w[MIDD * 3];
    float gf[MIDD], gx[MIDD];  // wf2^T b2
    float af[MIDD], betf[MIDD];
    float ax[MIDD], betx[MIDD];
    float am[CCH], bm[CCH];
    float m2b[CCH], wf2b[CCH], wx2b[CCH];
    float cf, cx;              // ||b2||^2
};

__global__ void __launch_bounds__(BLK) main_kernel(
    const float* __restrict__ o_p_fea, const float* __restrict__ p_xyz,
    const int*   __restrict__ idx_abs,
    const float* __restrict__ wf1w, const float* __restrict__ wf1b,
    const float* __restrict__ wfg,  const float* __restrict__ wfb,
    const float* __restrict__ wfm,  const float* __restrict__ wfv,
    const float* __restrict__ wf2w, const float* __restrict__ wf2b,
    const float* __restrict__ wx1w, const float* __restrict__ wx1b,
    const float* __restrict__ wxg,  const float* __restrict__ wxb,
    const float* __restrict__ wxm,  const float* __restrict__ wxv,
    const float* __restrict__ wx2w, const float* __restrict__ wx2b,
    const float* __restrict__ m1w,  const float* __restrict__ m1b,
    const float* __restrict__ mg,   const float* __restrict__ mbb,
    const float* __restrict__ mm,   const float* __restrict__ mv,
    const float* __restrict__ m2w,  const float* __restrict__ m2b)
{
    __shared__ SmemB sm;
    const int tid = threadIdx.x;

    // -------- phase 1: load weights, transpose wf2/wx2, fold BN --------
    for (int i = tid; i < CCH * CCH; i += BLK) { sm.m1w[i] = m1w[i]; sm.m2w[i] = m2w[i]; }
    for (int i = tid; i < MIDD * CCH; i += BLK) {
        sm.wf1w[i] = wf1w[i];
        int c = i >> 4, r = i & 15;                 // source is (C, MID) row-major
        sm.wf2t[r * CCH + c] = wf2w[i];
        sm.wx2t[r * CCH + c] = wx2w[i];
    }
    if (tid < MIDD * 3) sm.wx1w[tid] = wx1w[tid];
    if (tid < MIDD) {
        float a = wfg[tid] * rsqrtf(wfv[tid] + 1e-5f);
        sm.af[tid] = a;
        sm.betf[tid] = a * (wf1b[tid] - wfm[tid]) + wfb[tid];
        float a2 = wxg[tid] * rsqrtf(wxv[tid] + 1e-5f);
        sm.ax[tid] = a2;
        sm.betx[tid] = a2 * (wx1b[tid] - wxm[tid]) + wxb[tid];
    }
    if (tid < CCH) {
        float a = mg[tid] * rsqrtf(mv[tid] + 1e-5f);
        sm.am[tid] = a;
        sm.bm[tid] = a * (m1b[tid] - mm[tid]) + mbb[tid];
        sm.m2b[tid]  = m2b[tid];
        sm.wf2b[tid] = wf2b[tid];
        sm.wx2b[tid] = wx2b[tid];
    }
    __syncthreads();

    // -------- phase 2: Gram matrices + derived scalars --------
    for (int t = tid; t < MIDD * MIDD; t += BLK) {
        int i = t >> 4, j = t & 15;
        float sf = 0.f, sx = 0.f;
#pragma unroll
        for (int c = 0; c < CCH; c++) {
            sf += sm.wf2t[i * CCH + c] * sm.wf2t[j * CCH + c];
            sx += sm.wx2t[i * CCH + c] * sm.wx2t[j * CCH + c];
        }
        sm.Gf[t] = sf; sm.Gx[t] = sx;
    }
    if (tid < MIDD) {
        float s = 0.f;
#pragma unroll
        for (int c = 0; c < CCH; c++) s += sm.wf2t[tid * CCH + c] * sm.wf2b[c];
        sm.gf[tid] = s;
    } else if (tid < 2 * MIDD) {
        int t = tid - MIDD; float s = 0.f;
#pragma unroll
        for (int c = 0; c < CCH; c++) s += sm.wx2t[t * CCH + c] * sm.wx2b[c];
        sm.gx[t] = s;
    } else if (tid == 32) {
        float s = 0.f;
#pragma unroll
        for (int c = 0; c < CCH; c++) s += sm.wf2b[c] * sm.wf2b[c];
        sm.cf = s;
    } else if (tid == 33) {
        float s = 0.f;
#pragma unroll
        for (int c = 0; c < CCH; c++) s += sm.wx2b[c] * sm.wx2b[c];
        sm.cx = s;
    }
    __syncthreads();

    const int n = blockIdx.x * BLK + tid;   // exact: 1024*128 = NPTS

    // -------- phase A: point MLP + projections --------
    float p0[CCH];
    {
        const float4* pin = reinterpret_cast<const float4*>(o_p_fea + (size_t)n * CCH);
#pragma unroll
        for (int c4 = 0; c4 < 8; c4++) {
            float4 v = pin[c4];
            p0[c4 * 4 + 0] = v.x; p0[c4 * 4 + 1] = v.y;
            p0[c4 * 4 + 2] = v.z; p0[c4 * 4 + 3] = v.w;
        }
    }
    float h1[CCH];
#pragma unroll
    for (int c = 0; c < CCH; c++) {
        const float4* w = reinterpret_cast<const float4*>(sm.m1w + c * CCH);
        float s = 0.f;
#pragma unroll
        for (int c4 = 0; c4 < 8; c4++) {
            float4 wv = w[c4];
            s += p0[c4 * 4 + 0] * wv.x + p0[c4 * 4 + 1] * wv.y
               + p0[c4 * 4 + 2] * wv.z + p0[c4 * 4 + 3] * wv.w;
        }
        h1[c] = fmaxf(sm.am[c] * s + sm.bm[c], 0.f);
    }
    float pf[CCH]; float ss = 0.f;
#pragma unroll
    for (int c = 0; c < CCH; c++) {
        const float4* w = reinterpret_cast<const float4*>(sm.m2w + c * CCH);
        float s = sm.m2b[c];
#pragma unroll
        for (int c4 = 0; c4 < 8; c4++) {
            float4 wv = w[c4];
            s += h1[c4 * 4 + 0] * wv.x + h1[c4 * 4 + 1] * wv.y
               + h1[c4 * 4 + 2] * wv.z + h1[c4 * 4 + 3] * wv.w;
        }
        pf[c] = s; ss += s * s;
    }
    float inv = 1.f / fmaxf(sqrtf(ss), 1e-12f);

    float Vf[MIDD], Vx[MIDD];
#pragma unroll
    for (int i = 0; i < MIDD; i++) {
        const float4* wfr = reinterpret_cast<const float4*>(sm.wf2t + i * CCH);
        const float4* wxr = reinterpret_cast<const float4*>(sm.wx2t + i * CCH);
        float sf = 0.f, sx = 0.f;
#pragma unroll
        for (int c4 = 0; c4 < 8; c4++) {
            float4 a = wfr[c4], b = wxr[c4];
            sf += pf[c4 * 4 + 0] * a.x + pf[c4 * 4 + 1] * a.y
                + pf[c4 * 4 + 2] * a.z + pf[c4 * 4 + 3] * a.w;
            sx += pf[c4 * 4 + 0] * b.x + pf[c4 * 4 + 1] * b.y
                + pf[c4 * 4 + 2] * b.z + pf[c4 * 4 + 3] * b.w;
        }
        Vf[i] = sf * inv; Vx[i] = sx * inv;
    }
    float pbf = 0.f, pbx = 0.f;
#pragma unroll
    for (int c = 0; c < CCH; c++) { pbf += pf[c] * sm.wf2b[c]; pbx += pf[c] * sm.wx2b[c]; }
    pbf *= inv; pbx *= inv;

    float PHf[MIDD];
#pragma unroll
    for (int i = 0; i < MIDD; i++) {
        const float4* w = reinterpret_cast<const float4*>(sm.wf1w + i * CCH);
        float s = 0.f;
#pragma unroll
        for (int c4 = 0; c4 < 8; c4++) {
            float4 wv = w[c4];
            s += p0[c4 * 4 + 0] * wv.x + p0[c4 * 4 + 1] * wv.y
               + p0[c4 * 4 + 2] * wv.z + p0[c4 * 4 + 3] * wv.w;
        }
        PHf[i] = s;
    }
    const float x0 = p_xyz[(size_t)n * 3 + 0];
    const float x1 = p_xyz[(size_t)n * 3 + 1];
    const float x2 = p_xyz[(size_t)n * 3 + 2];
    float PHx[MIDD];
#pragma unroll
    for (int i = 0; i < MIDD; i++)
        PHx[i] = x0 * sm.wx1w[i * 3 + 0] + x1 * sm.wx1w[i * 3 + 1] + x2 * sm.wx1w[i * 3 + 2];

    int idxs[KNB];
#pragma unroll
    for (int k = 0; k < KNB; k++) idxs[k] = idx_abs[(size_t)n * KNB + k];

    float sc[KNB];

    // -------- phase B: fea path, k-groups of 3 (Gram rows amortized 3x) --------
#pragma unroll
    for (int g = 0; g < 2; g++) {
        float h[3][MIDD];
#pragma unroll
        for (int kk = 0; kk < 3; kk++) {
            const float4* src = reinterpret_cast<const float4*>(g_sphf + (size_t)idxs[g * 3 + kk] * MIDD);
#pragma unroll
            for (int i4 = 0; i4 < 4; i4++) {
                float4 v = src[i4];
                int b = i4 * 4;
                h[kk][b + 0] = fmaxf(sm.af[b + 0] * (v.x - PHf[b + 0]) + sm.betf[b + 0], 0.f);
                h[kk][b + 1] = fmaxf(sm.af[b + 1] * (v.y - PHf[b + 1]) + sm.betf[b + 1], 0.f);
                h[kk][b + 2] = fmaxf(sm.af[b + 2] * (v.z - PHf[b + 2]) + sm.betf[b + 2], 0.f);
                h[kk][b + 3] = fmaxf(sm.af[b + 3] * (v.w - PHf[b + 3]) + sm.betf[b + 3], 0.f);
            }
        }
        float d0 = pbf, d1 = pbf, d2 = pbf;
#pragma unroll
        for (int i = 0; i < MIDD; i++) {
            d0 += h[0][i] * Vf[i]; d1 += h[1][i] * Vf[i]; d2 += h[2][i] * Vf[i];
        }
        float q0 = sm.cf, q1 = sm.cf, q2 = sm.cf;
#pragma unroll
        for (int i = 0; i < MIDD; i++) {
            float row[MIDD];
            const float4* gr = reinterpret_cast<const float4*>(sm.Gf + i * MIDD);
#pragma unroll
            for (int j4 = 0; j4 < 4; j4++) {
                float4 v = gr[j4];
                row[j4 * 4 + 0] = v.x; row[j4 * 4 + 1] = v.y;
                row[j4 * 4 + 2] = v.z; row[j4 * 4 + 3] = v.w;
            }
            float tg = 2.f * sm.gf[i];
            float t0 = tg, t1 = tg, t2 = tg;
#pragma unroll
            for (int j = 0; j < MIDD; j++) {
                t0 += row[j] * h[0][j]; t1 += row[j] * h[1][j]; t2 += row[j] * h[2][j];
            }
            q0 += h[0][i] * t0; q1 += h[1][i] * t1; q2 += h[2][i] * t2;
        }
        sc[g * 3 + 0] = d0 / fmaxf(sqrtf(fmaxf(q0, 0.f)), 1e-12f);
        sc[g * 3 + 1] = d1 / fmaxf(sqrtf(fmaxf(q1, 0.f)), 1e-12f);
        sc[g * 3 + 2] = d2 / fmaxf(sqrtf(fmaxf(q2, 0.f)), 1e-12f);
    }

    // -------- phase C: xyz path --------
#pragma unroll
    for (int g = 0; g < 2; g++) {
        float h[3][MIDD];
#pragma unroll
        for (int kk = 0; kk < 3; kk++) {
            const float4* src = reinterpret_cast<const float4*>(g_sphx + (size_t)idxs[g * 3 + kk] * MIDD);
#pragma unroll
            for (int i4 = 0; i4 < 4; i4++) {
                float4 v = src[i4];
                int b = i4 * 4;
                h[kk][b + 0] = fmaxf(sm.ax[b + 0] * (v.x - PHx[b + 0]) + sm.betx[b + 0], 0.f);
                h[kk][b + 1] = fmaxf(sm.ax[b + 1] * (v.y - PHx[b + 1]) + sm.betx[b + 1], 0.f);
                h[kk][b + 2] = fmaxf(sm.ax[b + 2] * (v.z - PHx[b + 2]) + sm.betx[b + 2], 0.f);
                h[kk][b + 3] = fmaxf(sm.ax[b + 3] * (v.w - PHx[b + 3]) + sm.betx[b + 3], 0.f);
            }
        }
        float d0 = pbx, d1 = pbx, d2 = pbx;
#pragma unroll
        for (int i = 0; i < MIDD; i++) {
            d0 += h[0][i] * Vx[i]; d1 += h[1][i] * Vx[i]; d2 += h[2][i] * Vx[i];
        }
        float q0 = sm.cx, q1 = sm.cx, q2 = sm.cx;
#pragma unroll
        for (int i = 0; i < MIDD; i++) {
            float row[MIDD];
            const float4* gr = reinterpret_cast<const float4*>(sm.Gx + i * MIDD);
#pragma unroll
            for (int j4 = 0; j4 < 4; j4++) {
                float4 v = gr[j4];
                row[j4 * 4 + 0] = v.x; row[j4 * 4 + 1] = v.y;
                row[j4 * 4 + 2] = v.z; row[j4 * 4 + 3] = v.w;
            }
            float tg = 2.f * sm.gx[i];
            float t0 = tg, t1 = tg, t2 = tg;
#pragma unroll
            for (int j = 0; j < MIDD; j++) {
                t0 += row[j] * h[0][j]; t1 += row[j] * h[1][j]; t2 += row[j] * h[2][j];
            }
            q0 += h[0][i] * t0; q1 += h[1][i] * t1; q2 += h[2][i] * t2;
        }
        sc[g * 3 + 0] *= d0 / fmaxf(sqrtf(fmaxf(q0, 0.f)), 1e-12f);
        sc[g * 3 + 1] *= d1 / fmaxf(sqrtf(fmaxf(q1, 0.f)), 1e-12f);
        sc[g * 3 + 2] *= d2 / fmaxf(sqrtf(fmaxf(q2, 0.f)), 1e-12f);
    }

    // -------- softmax over K --------
    float mx = sc[0];
#pragma unroll
    for (int k = 1; k < KNB; k++) mx = fmaxf(mx, sc[k]);
    float esum = 0.f;
#pragma unroll
    for (int k = 0; k < KNB; k++) { sc[k] = __expf(sc[k] - mx); esum += sc[k]; }
    float isum = 1.f / esum;

    // -------- scatter (replicated vector reds) --------
    // reload p0 (registers were reused during phases B/C)
    {
        const float4* pin = reinterpret_cast<const float4*>(o_p_fea + (size_t)n * CCH);
#pragma unroll
        for (int c4 = 0; c4 < 8; c4++) {
            float4 v = pin[c4];
            p0[c4 * 4 + 0] = v.x; p0[c4 * 4 + 1] = v.y;
            p0[c4 * 4 + 2] = v.z; p0[c4 * 4 + 3] = v.w;
        }
    }
    const int rep = blockIdx.x & (RREP - 1);
    float* accbase = &g_acc[rep][0];
#pragma unroll
    for (int k = 0; k < KNB; k++) {
        float wk = sc[k] * isum;
        float* base = accbase + (size_t)idxs[k] * ACCW;
#pragma unroll
        for (int c = 0; c < CCH; c += 4) {
            asm volatile("red.global.add.v4.f32 [%0], {%1,%2,%3,%4};"
                         :: "l"(base + c),
                            "f"(p0[c] * wk), "f"(p0[c + 1] * wk),
                            "f"(p0[c + 2] * wk), "f"(p0[c + 3] * wk)
                         : "memory");
        }
        asm volatile("red.global.add.v4.f32 [%0], {%1,%2,%3,%4};"
                     :: "l"(base + CCH),
                        "f"(x0 * wk), "f"(x1 * wk), "f"(x2 * wk), "f"(wk)
                     : "memory");
    }
}

// ---------------- kernel 3: finalize (sum replicas, divide, write out) ----------------
__global__ void finalize_kernel(float* __restrict__ out) {
    int t = blockIdx.x * blockDim.x + threadIdx.x;   // MSEG*9 threads
    if (t >= MSEG * 9) return;
    int m = t / 9;
    int j = t - m * 9;          // which float4 column of the 36-float row

    // wsum across replicas (floats [32..35].w == index 35)
    float wsum = 0.f;
#pragma unroll
    for (int r = 0; r < RREP; r++) wsum += g_acc[r][m * ACCW + 35];
    float d = 1.f / (wsum + 1e-8f);

    float4 s = make_float4(0.f, 0.f, 0.f, 0.f);
#pragma unroll
    for (int r = 0; r < RREP; r++) {
        float4 v = *reinterpret_cast<const float4*>(&g_acc[r][m * ACCW + j * 4]);
        s.x += v.x; s.y += v.y; s.z += v.z; s.w += v.w;
    }
    if (j < 8) {
        float4 o = make_float4(s.x * d, s.y * d, s.z * d, s.w * d);
        *reinterpret_cast<float4*>(out + (size_t)m * CCH + j * 4) = o;
    } else {
        float* oxyz = out + (size_t)MSEG * CCH + (size_t)m * 3;
        oxyz[0] = s.x * d; oxyz[1] = s.y * d; oxyz[2] = s.z * d;
    }
}

// ---------------- launch ----------------
extern "C" void kernel_launch(void* const* d_in, const int* in_sizes, int n_in,
                              void* d_out, int out_size) {
    (void)in_sizes; (void)n_in; (void)out_size;
    const float* sp_fea  = (const float*)d_in[0];
    const float* sp_xyz  = (const float*)d_in[1];
    const float* o_p_fea = (const float*)d_in[2];
    const float* p_xyz   = (const float*)d_in[3];
    const int*   idx_abs = (const int*)d_in[4];
    // d_in[5] idx_rel (identical to idx_abs for bs=1), d_in[6] cluster_idx, d_in[7] offset: unused
    const float* wf1w = (const float*)d_in[8];
    const float* wf1b = (const float*)d_in[9];
    const float* wfg  = (const float*)d_in[10];
    const float* wfb  = (const float*)d_in[11];
    const float* wfm  = (const float*)d_in[12];
    const float* wfv  = (const float*)d_in[13];
    const float* wf2w = (const float*)d_in[14];
    const float* wf2b = (const float*)d_in[15];
    const float* wx1w = (const float*)d_in[16];
    const float* wx1b = (const float*)d_in[17];
    const float* wxg  = (const float*)d_in[18];
    const float* wxb  = (const float*)d_in[19];
    const float* wxm  = (const float*)d_in[20];
    const float* wxv  = (const float*)d_in[21];
    const float* wx2w = (const float*)d_in[22];
    const float* wx2b = (const float*)d_in[23];
    const float* m1w  = (const float*)d_in[24];
    const float* m1b  = (const float*)d_in[25];
    const float* mg   = (const float*)d_in[26];
    const float* mbb  = (const float*)d_in[27];
    const float* mm   = (const float*)d_in[28];
    const float* mv   = (const float*)d_in[29];
    const float* m2w  = (const float*)d_in[30];
    const float* m2b  = (const float*)d_in[31];

    pre_kernel<<<(MSEG + BLK - 1) / BLK, BLK>>>(sp_fea, sp_xyz, wf1w, wx1w);
    main_kernel<<<NPTS / BLK, BLK>>>(
        o_p_fea, p_xyz, idx_abs,
        wf1w, wf1b, wfg, wfb, wfm, wfv, wf2w, wf2b,
        wx1w, wx1b, wxg, wxb, wxm, wxv, wx2w, wx2b,
        m1w, m1b, mg, mbb, mm, mv, m2w, m2b);
    finalize_kernel<<<(MSEG * 9 + BLK - 1) / BLK, BLK>>>((float*)d_out);
}

// round 3
// speedup vs baseline: 2.3860x; 1.8282x over previous
#include <cuda_runtime.h>
#include <math.h>

#define NPTS 131072
#define MSEG 4096
#define CCH  32
#define MIDD 16
#define KNB  6
#define ACCW 36
#define RREP 8
#define BN_EPS 1e-5f

// ---------------- static device scratch ----------------
__device__ __align__(256) float g_sphf[MSEG * MIDD];       // af[i] * (sp_fea[m] . wf1[i])
__device__ __align__(256) float g_sphx[MSEG * MIDD];       // ax[i] * (sp_xyz[m] . wx1[i])
__device__ __align__(256) float g_acc [RREP][MSEG * ACCW];
__device__ __align__(256) float4 g_pp[17][NPTS];           // planar per-point data

struct Prm {
    float Of[MIDD * MIDD];   // row i: j<i doubled off-diag, j==i diag, j>i zero
    float Ox[MIDD * MIDD];
    float g2f[MIDD], g2x[MIDD];  // 2 * W2^T b2
    float cf, cx;                // ||b2||^2
};
__device__ Prm g_prm;

// ---------------- setup: Gram constants (1 block) ----------------
__global__ void setup_kernel(const float* __restrict__ wf2w, const float* __restrict__ wf2b,
                             const float* __restrict__ wx2w, const float* __restrict__ wx2b) {
    int t = threadIdx.x;            // 256 threads
    int i = t >> 4, j = t & 15;
    float sf = 0.f, sx = 0.f;
#pragma unroll
    for (int c = 0; c < CCH; c++) {
        sf += wf2w[c * MIDD + i] * wf2w[c * MIDD + j];
        sx += wx2w[c * MIDD + i] * wx2w[c * MIDD + j];
    }
    g_prm.Of[t] = (j < i) ? 2.f * sf : (j == i ? sf : 0.f);
    g_prm.Ox[t] = (j < i) ? 2.f * sx : (j == i ? sx : 0.f);
    if (t < MIDD) {
        float s = 0.f;
#pragma unroll
        for (int c = 0; c < CCH; c++) s += wf2w[c * MIDD + t] * wf2b[c];
        g_prm.g2f[t] = 2.f * s;
    } else if (t < 2 * MIDD) {
        int u = t - MIDD; float s = 0.f;
#pragma unroll
        for (int c = 0; c < CCH; c++) s += wx2w[c * MIDD + u] * wx2b[c];
        g_prm.g2x[u] = 2.f * s;
    } else if (t == 32) {
        float s = 0.f;
#pragma unroll
        for (int c = 0; c < CCH; c++) s += wf2b[c] * wf2b[c];
        g_prm.cf = s;
    } else if (t == 33) {
        float s = 0.f;
#pragma unroll
        for (int c = 0; c < CCH; c++) s += wx2b[c] * wx2b[c];
        g_prm.cx = s;
    }
}

// ---------------- sp_pre: scaled superpoint projections + zero accumulators ----------------
__global__ void sp_pre_kernel(const float* __restrict__ sp_fea, const float* __restrict__ sp_xyz,
                              const float* __restrict__ wf1w, const float* __restrict__ wx1w,
                              const float* __restrict__ wfg,  const float* __restrict__ wfv,
                              const float* __restrict__ wxg,  const float* __restrict__ wxv) {
    int t = blockIdx.x * blockDim.x + threadIdx.x;   // 65536 threads: (m, i)
    int m = t >> 4, i = t & 15;

    float af = __ldg(wfg + i) * rsqrtf(__ldg(wfv + i) + BN_EPS);
    float ax = __ldg(wxg + i) * rsqrtf(__ldg(wxv + i) + BN_EPS);

    float s = 0.f;
    const float4* fr = reinterpret_cast<const float4*>(sp_fea + m * CCH);
    const float4* wr = reinterpret_cast<const float4*>(wf1w + i * CCH);
#pragma unroll
    for (int c4 = 0; c4 < 8; c4++) {
        float4 a = fr[c4], b = wr[c4];
        s += a.x * b.x + a.y * b.y + a.z * b.z + a.w * b.w;
    }
    g_sphf[t] = af * s;
    g_sphx[t] = ax * (__ldg(sp_xyz + m * 3 + 0) * __ldg(wx1w + i * 3 + 0)
                    + __ldg(sp_xyz + m * 3 + 1) * __ldg(wx1w + i * 3 + 1)
                    + __ldg(sp_xyz + m * 3 + 2) * __ldg(wx1w + i * 3 + 2));

    // zero accumulators (grid-stride, float4)
    float4* pacc = reinterpret_cast<float4*>(&g_acc[0][0]);
    const int tot4 = RREP * MSEG * ACCW / 4;
    float4 z = make_float4(0.f, 0.f, 0.f, 0.f);
    for (int j = t; j < tot4; j += 65536) pacc[j] = z;
}

// ---------------- kernel A: per-point prep ----------------
struct __align__(16) SmemA {
    float m1w [CCH * CCH];
    float m2w [CCH * CCH];
    float wf1w[MIDD * CCH];
    float wf2t[MIDD * CCH];   // transposed: [i*32+c]
    float wx2t[MIDD * CCH];
    float wx1w[MIDD * 3];
    float am[CCH], bm[CCH], m2b[CCH], wf2b[CCH], wx2b[CCH];
    float af[MIDD], betf[MIDD], ax[MIDD], betx[MIDD];
};

__global__ void __launch_bounds__(256, 2) prep_kernel(
    const float* __restrict__ o_p_fea, const float* __restrict__ p_xyz,
    const float* __restrict__ wf1w, const float* __restrict__ wf1b,
    const float* __restrict__ wfg,  const float* __restrict__ wfb,
    const float* __restrict__ wfm,  const float* __restrict__ wfv,
    const float* __restrict__ wf2w, const float* __restrict__ wf2b,
    const float* __restrict__ wx1w, const float* __restrict__ wx1b,
    const float* __restrict__ wxg,  const float* __restrict__ wxb,
    const float* __restrict__ wxm,  const float* __restrict__ wxv,
    const float* __restrict__ wx2w, const float* __restrict__ wx2b,
    const float* __restrict__ m1w,  const float* __restrict__ m1b,
    const float* __restrict__ mg,   const float* __restrict__ mbb,
    const float* __restrict__ mm,   const float* __restrict__ mv,
    const float* __restrict__ m2w,  const float* __restrict__ m2b)
{
    __shared__ SmemA sm;
    const int tid = threadIdx.x;
    for (int i = tid; i < CCH * CCH; i += 256) { sm.m1w[i] = m1w[i]; sm.m2w[i] = m2w[i]; }
    for (int i = tid; i < MIDD * CCH; i += 256) {
        sm.wf1w[i] = wf1w[i];
        int c = i >> 4, r = i & 15;
        sm.wf2t[r * CCH + c] = wf2w[i];
        sm.wx2t[r * CCH + c] = wx2w[i];
    }
    if (tid < MIDD * 3) sm.wx1w[tid] = wx1w[tid];
    if (tid < MIDD) {
        float a = wfg[tid] * rsqrtf(wfv[tid] + BN_EPS);
        sm.af[tid] = a;
        sm.betf[tid] = a * (wf1b[tid] - wfm[tid]) + wfb[tid];
        float a2 = wxg[tid] * rsqrtf(wxv[tid] + BN_EPS);
        sm.ax[tid] = a2;
        sm.betx[tid] = a2 * (wx1b[tid] - wxm[tid]) + wxb[tid];
    }
    if (tid < CCH) {
        float a = mg[tid] * rsqrtf(mv[tid] + BN_EPS);
        sm.am[tid] = a;
        sm.bm[tid] = a * (m1b[tid] - mm[tid]) + mbb[tid];
        sm.m2b[tid]  = m2b[tid];
        sm.wf2b[tid] = wf2b[tid];
        sm.wx2b[tid] = wx2b[tid];
    }
    __syncthreads();

    const int n = blockIdx.x * 256 + tid;

    float p0[CCH];
    {
        const float4* pin = reinterpret_cast<const float4*>(o_p_fea + (size_t)n * CCH);
#pragma unroll
        for (int c4 = 0; c4 < 8; c4++) {
            float4 v = pin[c4];
            p0[c4 * 4 + 0] = v.x; p0[c4 * 4 + 1] = v.y;
            p0[c4 * 4 + 2] = v.z; p0[c4 * 4 + 3] = v.w;
        }
    }

    // BF = betf - af * (p0 . wf1[i])  -> planes 8..11
#pragma unroll
    for (int i4 = 0; i4 < 4; i4++) {
        float4 o;
        float* op = &o.x;
#pragma unroll
        for (int q = 0; q < 4; q++) {
            int i = i4 * 4 + q;
            const float4* w = reinterpret_cast<const float4*>(sm.wf1w + i * CCH);
            float s0 = 0.f, s1 = 0.f;
#pragma unroll
            for (int c4 = 0; c4 < 8; c4 += 2) {
                float4 a = w[c4], b = w[c4 + 1];
                s0 += p0[c4 * 4 + 0] * a.x + p0[c4 * 4 + 1] * a.y
                    + p0[c4 * 4 + 2] * a.z + p0[c4 * 4 + 3] * a.w;
                s1 += p0[c4 * 4 + 4] * b.x + p0[c4 * 4 + 5] * b.y
                    + p0[c4 * 4 + 6] * b.z + p0[c4 * 4 + 7] * b.w;
            }
            op[q] = sm.betf[i] - sm.af[i] * (s0 + s1);
        }
        g_pp[8 + i4][n] = o;
    }
    // BX = betx - ax * (xyz . wx1[i]) -> planes 12..15
    {
        float x0 = p_xyz[(size_t)n * 3 + 0];
        float x1 = p_xyz[(size_t)n * 3 + 1];
        float x2 = p_xyz[(size_t)n * 3 + 2];
#pragma unroll
        for (int i4 = 0; i4 < 4; i4++) {
            float4 o; float* op = &o.x;
#pragma unroll
            for (int q = 0; q < 4; q++) {
                int i = i4 * 4 + q;
                float s = x0 * sm.wx1w[i * 3 + 0] + x1 * sm.wx1w[i * 3 + 1] + x2 * sm.wx1w[i * 3 + 2];
                op[q] = sm.betx[i] - sm.ax[i] * s;
            }
            g_pp[12 + i4][n] = o;
        }
    }

    // point MLP
    float h1[CCH];
#pragma unroll
    for (int c = 0; c < CCH; c++) {
        const float4* w = reinterpret_cast<const float4*>(sm.m1w + c * CCH);
        float s0 = 0.f, s1 = 0.f;
#pragma unroll
        for (int c4 = 0; c4 < 8; c4 += 2) {
            float4 a = w[c4], b = w[c4 + 1];
            s0 += p0[c4 * 4 + 0] * a.x + p0[c4 * 4 + 1] * a.y
                + p0[c4 * 4 + 2] * a.z + p0[c4 * 4 + 3] * a.w;
            s1 += p0[c4 * 4 + 4] * b.x + p0[c4 * 4 + 5] * b.y
                + p0[c4 * 4 + 6] * b.z + p0[c4 * 4 + 7] * b.w;
        }
        h1[c] = fmaxf(sm.am[c] * (s0 + s1) + sm.bm[c], 0.f);
    }
    float pf[CCH]; float ss = 0.f;
#pragma unroll
    for (int c = 0; c < CCH; c++) {
        const float4* w = reinterpret_cast<const float4*>(sm.m2w + c * CCH);
        float s0 = sm.m2b[c], s1 = 0.f;
#pragma unroll
        for (int c4 = 0; c4 < 8; c4 += 2) {
            float4 a = w[c4], b = w[c4 + 1];
            s0 += h1[c4 * 4 + 0] * a.x + h1[c4 * 4 + 1] * a.y
                + h1[c4 * 4 + 2] * a.z + h1[c4 * 4 + 3] * a.w;
            s1 += h1[c4 * 4 + 4] * b.x + h1[c4 * 4 + 5] * b.y
                + h1[c4 * 4 + 6] * b.z + h1[c4 * 4 + 7] * b.w;
        }
        float s = s0 + s1;
        pf[c] = s; ss += s * s;
    }
    float inv = 1.f / fmaxf(sqrtf(ss), 1e-12f);

    // Vf -> planes 0..3, Vx -> planes 4..7
#pragma unroll
    for (int i4 = 0; i4 < 4; i4++) {
        float4 of, ox;
        float* ofp = &of.x; float* oxp = &ox.x;
#pragma unroll
        for (int q = 0; q < 4; q++) {
            int i = i4 * 4 + q;
            const float4* wfr = reinterpret_cast<const float4*>(sm.wf2t + i * CCH);
            const float4* wxr = reinterpret_cast<const float4*>(sm.wx2t + i * CCH);
            float sf = 0.f, sx = 0.f;
#pragma unroll
            for (int c4 = 0; c4 < 8; c4++) {
                float4 a = wfr[c4], b = wxr[c4];
                sf += pf[c4 * 4 + 0] * a.x + pf[c4 * 4 + 1] * a.y
                    + pf[c4 * 4 + 2] * a.z + pf[c4 * 4 + 3] * a.w;
                sx += pf[c4 * 4 + 0] * b.x + pf[c4 * 4 + 1] * b.y
                    + pf[c4 * 4 + 2] * b.z + pf[c4 * 4 + 3] * b.w;
            }
            ofp[q] = sf * inv; oxp[q] = sx * inv;
        }
        g_pp[0 + i4][n] = of;
        g_pp[4 + i4][n] = ox;
    }
    float pbf = 0.f, pbx = 0.f;
#pragma unroll
    for (int c = 0; c < CCH; c++) { pbf += pf[c] * sm.wf2b[c]; pbx += pf[c] * sm.wx2b[c]; }
    g_pp[16][n] = make_float4(pbf * inv, pbx * inv, 0.f, 0.f);
}

// ---------------- kernel B: scores + softmax + scatter ----------------
__global__ void __launch_bounds__(128, 4) score_kernel(
    const float* __restrict__ o_p_fea, const float* __restrict__ p_xyz,
    const int* __restrict__ idx_abs)
{
    __shared__ float sprm[sizeof(Prm) / 4];
    const int tid = threadIdx.x;
    {
        const float* src = reinterpret_cast<const float*>(&g_prm);
        for (int i = tid; i < (int)(sizeof(Prm) / 4); i += 128) sprm[i] = src[i];
    }
    __syncthreads();
    const float* Of  = sprm;
    const float* Ox  = sprm + MIDD * MIDD;
    const float* g2f = sprm + 2 * MIDD * MIDD;
    const float* g2x = g2f + MIDD;
    const float  cf  = g2x[MIDD];   // Prm layout: cf right after g2x
    const float  cx  = g2x[MIDD + 1];

    const int n = blockIdx.x * 128 + tid;

    float Vf[MIDD], Vx[MIDD], BF[MIDD], BX[MIDD];
#pragma unroll
    for (int i4 = 0; i4 < 4; i4++) {
        float4 a = g_pp[0 + i4][n];
        Vf[i4 * 4 + 0] = a.x; Vf[i4 * 4 + 1] = a.y; Vf[i4 * 4 + 2] = a.z; Vf[i4 * 4 + 3] = a.w;
        float4 b = g_pp[4 + i4][n];
        Vx[i4 * 4 + 0] = b.x; Vx[i4 * 4 + 1] = b.y; Vx[i4 * 4 + 2] = b.z; Vx[i4 * 4 + 3] = b.w;
        float4 c = g_pp[8 + i4][n];
        BF[i4 * 4 + 0] = c.x; BF[i4 * 4 + 1] = c.y; BF[i4 * 4 + 2] = c.z; BF[i4 * 4 + 3] = c.w;
        float4 d = g_pp[12 + i4][n];
        BX[i4 * 4 + 0] = d.x; BX[i4 * 4 + 1] = d.y; BX[i4 * 4 + 2] = d.z; BX[i4 * 4 + 3] = d.w;
    }
    float4 pb4 = g_pp[16][n];
    const float pbf = pb4.x, pbx = pb4.y;

    int idxs[KNB];
#pragma unroll
    for (int k = 0; k < KNB; k++) idxs[k] = idx_abs[(size_t)n * KNB + k];

    float sc[KNB];
#pragma unroll
    for (int k = 0; k < KNB; k++) {
        const float4* srf = reinterpret_cast<const float4*>(g_sphf + (size_t)idxs[k] * MIDD);
        const float4* srx = reinterpret_cast<const float4*>(g_sphx + (size_t)idxs[k] * MIDD);
        float hf[MIDD], hx[MIDD];
#pragma unroll
        for (int i4 = 0; i4 < 4; i4++) {
            float4 a = srf[i4], b = srx[i4];
            int q = i4 * 4;
            hf[q + 0] = fmaxf(a.x + BF[q + 0], 0.f);
            hf[q + 1] = fmaxf(a.y + BF[q + 1], 0.f);
            hf[q + 2] = fmaxf(a.z + BF[q + 2], 0.f);
            hf[q + 3] = fmaxf(a.w + BF[q + 3], 0.f);
            hx[q + 0] = fmaxf(b.x + BX[q + 0], 0.f);
            hx[q + 1] = fmaxf(b.y + BX[q + 1], 0.f);
            hx[q + 2] = fmaxf(b.z + BX[q + 2], 0.f);
            hx[q + 3] = fmaxf(b.w + BX[q + 3], 0.f);
        }
        float df = pbf, dx = pbx;
#pragma unroll
        for (int i = 0; i < MIDD; i++) { df += hf[i] * Vf[i]; dx += hx[i] * Vx[i]; }
        // symmetric half quadratic forms
        float qf = cf, qx = cx;
#pragma unroll
        for (int i = 0; i < MIDD; i++) {
            float tf = g2f[i] + Of[i * MIDD + i] * hf[i];
            float tx = g2x[i] + Ox[i * MIDD + i] * hx[i];
#pragma unroll
            for (int j = 0; j < i; j++) {
                tf += Of[i * MIDD + j] * hf[j];
                tx += Ox[i * MIDD + j] * hx[j];
            }
            qf += hf[i] * tf; qx += hx[i] * tx;
        }
        float nf = fmaxf(sqrtf(fmaxf(qf, 0.f)), 1e-12f);
        float nx = fmaxf(sqrtf(fmaxf(qx, 0.f)), 1e-12f);
        sc[k] = (df / nf) * (dx / nx);
    }

    float mx = sc[0];
#pragma unroll
    for (int k = 1; k < KNB; k++) mx = fmaxf(mx, sc[k]);
    float esum = 0.f;
#pragma unroll
    for (int k = 0; k < KNB; k++) { sc[k] = __expf(sc[k] - mx); esum += sc[k]; }
    float isum = 1.f / esum;

    // reload p0 / xyz for the scatter
    float p0[CCH];
    {
        const float4* pin = reinterpret_cast<const float4*>(o_p_fea + (size_t)n * CCH);
#pragma unroll
        for (int c4 = 0; c4 < 8; c4++) {
            float4 v = pin[c4];
            p0[c4 * 4 + 0] = v.x; p0[c4 * 4 + 1] = v.y;
            p0[c4 * 4 + 2] = v.z; p0[c4 * 4 + 3] = v.w;
        }
    }
    const float x0 = p_xyz[(size_t)n * 3 + 0];
    const float x1 = p_xyz[(size_t)n * 3 + 1];
    const float x2 = p_xyz[(size_t)n * 3 + 2];

    float* accbase = &g_acc[blockIdx.x & (RREP - 1)][0];
#pragma unroll
    for (int k = 0; k < KNB; k++) {
        float wk = sc[k] * isum;
        float* base = accbase + (size_t)idxs[k] * ACCW;
#pragma unroll
        for (int c = 0; c < CCH; c += 4) {
            asm volatile("red.global.add.v4.f32 [%0], {%1,%2,%3,%4};"
                         :: "l"(base + c),
                            "f"(p0[c] * wk), "f"(p0[c + 1] * wk),
                            "f"(p0[c + 2] * wk), "f"(p0[c + 3] * wk)
                         : "memory");
        }
        asm volatile("red.global.add.v4.f32 [%0], {%1,%2,%3,%4};"
                     :: "l"(base + CCH),
                        "f"(x0 * wk), "f"(x1 * wk), "f"(x2 * wk), "f"(wk)
                     : "memory");
    }
}

// ---------------- finalize ----------------
__global__ void finalize_kernel(float* __restrict__ out) {
    int t = blockIdx.x * blockDim.x + threadIdx.x;
    if (t >= MSEG * 9) return;
    int m = t / 9;
    int j = t - m * 9;

    float wsum = 0.f;
#pragma unroll
    for (int r = 0; r < RREP; r++) wsum += g_acc[r][m * ACCW + 35];
    float d = 1.f / (wsum + 1e-8f);

    float4 s = make_float4(0.f, 0.f, 0.f, 0.f);
#pragma unroll
    for (int r = 0; r < RREP; r++) {
        float4 v = *reinterpret_cast<const float4*>(&g_acc[r][m * ACCW + j * 4]);
        s.x += v.x; s.y += v.y; s.z += v.z; s.w += v.w;
    }
    if (j < 8) {
        *reinterpret_cast<float4*>(out + (size_t)m * CCH + j * 4) =
            make_float4(s.x * d, s.y * d, s.z * d, s.w * d);
    } else {
        float* oxyz = out + (size_t)MSEG * CCH + (size_t)m * 3;
        oxyz[0] = s.x * d; oxyz[1] = s.y * d; oxyz[2] = s.z * d;
    }
}

// ---------------- launch ----------------
extern "C" void kernel_launch(void* const* d_in, const int* in_sizes, int n_in,
                              void* d_out, int out_size) {
    (void)in_sizes; (void)n_in; (void)out_size;
    const float* sp_fea  = (const float*)d_in[0];
    const float* sp_xyz  = (const float*)d_in[1];
    const float* o_p_fea = (const float*)d_in[2];
    const float* p_xyz   = (const float*)d_in[3];
    const int*   idx_abs = (const int*)d_in[4];
    const float* wf1w = (const float*)d_in[8];
    const float* wf1b = (const float*)d_in[9];
    const float* wfg  = (const float*)d_in[10];
    const float* wfb  = (const float*)d_in[11];
    const float* wfm  = (const float*)d_in[12];
    const float* wfv  = (const float*)d_in[13];
    const float* wf2w = (const float*)d_in[14];
    const float* wf2b = (const float*)d_in[15];
    const float* wx1w = (const float*)d_in[16];
    const float* wx1b = (const float*)d_in[17];
    const float* wxg  = (const float*)d_in[18];
    const float* wxb  = (const float*)d_in[19];
    const float* wxm  = (const float*)d_in[20];
    const float* wxv  = (const float*)d_in[21];
    const float* wx2w = (const float*)d_in[22];
    const float* wx2b = (const float*)d_in[23];
    const float* m1w  = (const float*)d_in[24];
    const float* m1b  = (const float*)d_in[25];
    const float* mg   = (const float*)d_in[26];
    const float* mbb  = (const float*)d_in[27];
    const float* mm   = (const float*)d_in[28];
    const float* mv   = (const float*)d_in[29];
    const float* m2w  = (const float*)d_in[30];
    const float* m2b  = (const float*)d_in[31];

    setup_kernel<<<1, 256>>>(wf2w, wf2b, wx2w, wx2b);
    sp_pre_kernel<<<256, 256>>>(sp_fea, sp_xyz, wf1w, wx1w, wfg, wfv, wxg, wxv);
    prep_kernel<<<NPTS / 256, 256>>>(
        o_p_fea, p_xyz,
        wf1w, wf1b, wfg, wfb, wfm, wfv, wf2w, wf2b,
        wx1w, wx1b, wxg, wxb, wxm, wxv, wx2w, wx2b,
        m1w, m1b, mg, mbb, mm, mv, m2w, m2b);
    score_kernel<<<NPTS / 128, 128>>>(o_p_fea, p_xyz, idx_abs);
    finalize_kernel<<<(MSEG * 9 + 127) / 128, 128>>>((float*)d_out);
}